// round 4
// baseline (speedup 1.0000x reference)
#include <cuda_runtime.h>
#include <stdint.h>

#define BB 64
#define TT 256
#define NN 64
#define XPAD 68
#define ROWB (XPAD * 4)           // 272 bytes per xs row
#define BPAD 68                   // padded bits row stride (u32)

__device__ int g_H[NN * NN];      // Hamming accumulators (i<j)

// ---------------- fused: hierarchical bitpack + XOR/popcount Gram ------------
// Pair layout (63 words/col): level h = MSB of a^b.
//  w 0..31  (L5): w=a (0..31), bit s <-> b=32+s
//  w 32..47 (L4): blk=w16>>3, widx=w16&7; a=32blk+2widx+(s>>4), b=32blk+16+(s&15)
//  w 48..55 (L3): blk=w8>>1, widx=w8&1;  a=16blk+4widx+(s>>3), b=16blk+8+(s&7)
//  w 56..59 (L2): blk=2q+(s>>4); a=8blk+((s>>2)&3), b=8blk+4+(s&3)
//  w 60..61 (L1): blk=8q+(s>>2); a=4blk+((s>>1)&1), b=4blk+2+(s&1)
//  w 62     (L0): a=2s, b=2s+1
__global__ __launch_bounds__(512) void fusedKD(const float* __restrict__ in) {
    __shared__ __align__(16) float xs[BB][XPAD];      // 17.4 KB
    __shared__ __align__(16) uint32_t bitss[63 * BPAD]; // 17.1 KB
    __shared__ uint32_t gt[224];                      // byte-offset pairs, w56..62
    int tid = threadIdx.x;
    int t = blockIdx.x;

    // Load 64x64 slab (coalesced float4) into padded rows.
    {
        const float4* src = (const float4*)in;
        for (int q = tid; q < BB * 16; q += 512) {
            int b = q >> 4, c = q & 15;
            *(float4*)&xs[b][c * 4] = src[(size_t)b * (TT * 16) + t * 16 + c];
        }
    }
    // Small-level pair table (224 entries).
    if (tid < 224) {
        int w7 = tid >> 5, s = tid & 31;
        int a, b;
        if (w7 < 4)      { int blk = 2 * w7 + (s >> 4); a = 8 * blk + ((s >> 2) & 3); b = 8 * blk + 4 + (s & 3); }
        else if (w7 < 6) { int blk = 8 * (w7 - 4) + (s >> 2); a = 4 * blk + ((s >> 1) & 1); b = 4 * blk + 2 + (s & 1); }
        else             { a = 2 * s; b = 2 * s + 1; }
        gt[tid] = (uint32_t)(a * ROWB) | ((uint32_t)(b * ROWB) << 16);
    }
    __syncthreads();

    const char* xbase = (const char*)xs;

    // ---- specialized packers: exactly 512 tasks ----
    if (tid < 128) {                       // L5: (ag 0..7) x (cg 0..15)
        int ag = tid >> 4, cg = tid & 15;
        const char* xb = xbase + cg * 16;
        float4 fa0 = *(const float4*)(xb + (4 * ag + 0) * ROWB);
        float4 fa1 = *(const float4*)(xb + (4 * ag + 1) * ROWB);
        float4 fa2 = *(const float4*)(xb + (4 * ag + 2) * ROWB);
        float4 fa3 = *(const float4*)(xb + (4 * ag + 3) * ROWB);
        uint32_t w0[4] = {0,0,0,0}, w1[4] = {0,0,0,0}, w2[4] = {0,0,0,0}, w3[4] = {0,0,0,0};
        #pragma unroll
        for (int s = 0; s < 32; s++) {
            float4 fb = *(const float4*)(xb + (32 + s) * ROWB);
            uint32_t m = 1u << s;
            w0[0] |= (fa0.x > fb.x) ? m : 0u; w0[1] |= (fa0.y > fb.y) ? m : 0u;
            w0[2] |= (fa0.z > fb.z) ? m : 0u; w0[3] |= (fa0.w > fb.w) ? m : 0u;
            w1[0] |= (fa1.x > fb.x) ? m : 0u; w1[1] |= (fa1.y > fb.y) ? m : 0u;
            w1[2] |= (fa1.z > fb.z) ? m : 0u; w1[3] |= (fa1.w > fb.w) ? m : 0u;
            w2[0] |= (fa2.x > fb.x) ? m : 0u; w2[1] |= (fa2.y > fb.y) ? m : 0u;
            w2[2] |= (fa2.z > fb.z) ? m : 0u; w2[3] |= (fa2.w > fb.w) ? m : 0u;
            w3[0] |= (fa3.x > fb.x) ? m : 0u; w3[1] |= (fa3.y > fb.y) ? m : 0u;
            w3[2] |= (fa3.z > fb.z) ? m : 0u; w3[3] |= (fa3.w > fb.w) ? m : 0u;
        }
        *(uint4*)&bitss[(4*ag+0) * BPAD + 4*cg] = make_uint4(w0[0], w0[1], w0[2], w0[3]);
        *(uint4*)&bitss[(4*ag+1) * BPAD + 4*cg] = make_uint4(w1[0], w1[1], w1[2], w1[3]);
        *(uint4*)&bitss[(4*ag+2) * BPAD + 4*cg] = make_uint4(w2[0], w2[1], w2[2], w2[3]);
        *(uint4*)&bitss[(4*ag+3) * BPAD + 4*cg] = make_uint4(w3[0], w3[1], w3[2], w3[3]);
    } else if (tid < 384) {                // L4: (word16 0..15) x (cg 0..15)
        int idx = tid - 128;
        int w16 = idx >> 4, cg = idx & 15;
        int blk = w16 >> 3, widx = w16 & 7, base = 32 * blk;
        const char* xb = xbase + cg * 16;
        float4 fa0 = *(const float4*)(xb + (base + 2 * widx) * ROWB);
        float4 fa1 = *(const float4*)(xb + (base + 2 * widx + 1) * ROWB);
        uint32_t w[4] = {0,0,0,0};
        #pragma unroll
        for (int bb = 0; bb < 16; bb++) {
            float4 fb = *(const float4*)(xb + (base + 16 + bb) * ROWB);
            uint32_t mlo = 1u << bb, mhi = 1u << (16 + bb);
            w[0] |= ((fa0.x > fb.x) ? mlo : 0u) | ((fa1.x > fb.x) ? mhi : 0u);
            w[1] |= ((fa0.y > fb.y) ? mlo : 0u) | ((fa1.y > fb.y) ? mhi : 0u);
            w[2] |= ((fa0.z > fb.z) ? mlo : 0u) | ((fa1.z > fb.z) ? mhi : 0u);
            w[3] |= ((fa0.w > fb.w) ? mlo : 0u) | ((fa1.w > fb.w) ? mhi : 0u);
        }
        *(uint4*)&bitss[(32 + w16) * BPAD + 4*cg] = make_uint4(w[0], w[1], w[2], w[3]);
    } else {                               // L3: (word8 0..7) x (cg 0..15)
        int idx = tid - 384;
        int w8 = idx >> 4, cg = idx & 15;
        int blk = w8 >> 1, widx = w8 & 1, base = 16 * blk;
        const char* xb = xbase + cg * 16;
        float4 fa0 = *(const float4*)(xb + (base + 4 * widx + 0) * ROWB);
        float4 fa1 = *(const float4*)(xb + (base + 4 * widx + 1) * ROWB);
        float4 fa2 = *(const float4*)(xb + (base + 4 * widx + 2) * ROWB);
        float4 fa3 = *(const float4*)(xb + (base + 4 * widx + 3) * ROWB);
        uint32_t w[4] = {0,0,0,0};
        #pragma unroll
        for (int bb = 0; bb < 8; bb++) {
            float4 fb = *(const float4*)(xb + (base + 8 + bb) * ROWB);
            uint32_t m0 = 1u << bb, m1 = 1u << (8+bb), m2 = 1u << (16+bb), m3 = 1u << (24+bb);
            w[0] |= ((fa0.x>fb.x)?m0:0u)|((fa1.x>fb.x)?m1:0u)|((fa2.x>fb.x)?m2:0u)|((fa3.x>fb.x)?m3:0u);
            w[1] |= ((fa0.y>fb.y)?m0:0u)|((fa1.y>fb.y)?m1:0u)|((fa2.y>fb.y)?m2:0u)|((fa3.y>fb.y)?m3:0u);
            w[2] |= ((fa0.z>fb.z)?m0:0u)|((fa1.z>fb.z)?m1:0u)|((fa2.z>fb.z)?m2:0u)|((fa3.z>fb.z)?m3:0u);
            w[3] |= ((fa0.w>fb.w)?m0:0u)|((fa1.w>fb.w)?m1:0u)|((fa2.w>fb.w)?m2:0u)|((fa3.w>fb.w)?m3:0u);
        }
        *(uint4*)&bitss[(48 + w8) * BPAD + 4*cg] = make_uint4(w[0], w[1], w[2], w[3]);
    }
    // small levels: 7 words, table-driven
    if (tid < 112) {
        int w7 = tid >> 4, cg = tid & 15;
        const char* xb = xbase + cg * 16;
        const uint32_t* g = &gt[w7 << 5];
        uint32_t w[4] = {0,0,0,0};
        #pragma unroll
        for (int s = 0; s < 32; s++) {
            uint32_t u = g[s];
            float4 fa = *(const float4*)(xb + (u & 0xFFFFu));
            float4 fb = *(const float4*)(xb + (u >> 16));
            uint32_t m = 1u << s;
            w[0] |= (fa.x > fb.x) ? m : 0u;
            w[1] |= (fa.y > fb.y) ? m : 0u;
            w[2] |= (fa.z > fb.z) ? m : 0u;
            w[3] |= (fa.w > fb.w) ? m : 0u;
        }
        *(uint4*)&bitss[(56 + w7) * BPAD + 4*cg] = make_uint4(w[0], w[1], w[2], w[3]);
    }
    __syncthreads();

    // ---- Gram: 136 upper-tri 4x4 tiles x 2 word-chunks = 272 tasks ----
    if (tid < 272) {
        int tile = tid >> 1, chunk = tid & 1;
        int ti = 0, rem = tile;
        while (rem >= 16 - ti) { rem -= 16 - ti; ti++; }
        int tj = ti + rem;
        int i0 = ti << 2, j0 = tj << 2;
        int wbeg = chunk ? 32 : 0;
        int wend = chunk ? 63 : 32;

        int acc[16];
        #pragma unroll
        for (int k = 0; k < 16; k++) acc[k] = 0;
        #pragma unroll 4
        for (int w = wbeg; w < wend; w++) {
            uint4 bi = *(const uint4*)&bitss[w * BPAD + i0];
            uint4 bj = *(const uint4*)&bitss[w * BPAD + j0];
            uint32_t iv[4] = {bi.x, bi.y, bi.z, bi.w};
            uint32_t jv[4] = {bj.x, bj.y, bj.z, bj.w};
            #pragma unroll
            for (int ii = 0; ii < 4; ii++)
                #pragma unroll
                for (int jj = 0; jj < 4; jj++)
                    acc[ii * 4 + jj] += __popc(iv[ii] ^ jv[jj]);
        }
        #pragma unroll
        for (int k = 0; k < 16; k++) {
            int i = i0 + (k >> 2), j = j0 + (k & 3);
            if (i < j) atomicAdd(&g_H[i * NN + j], acc[k]);
        }
    }
}

// ---------------- distance + broadcast ----------------
__global__ __launch_bounds__(256) void phase3(float* __restrict__ out) {
    __shared__ __align__(16) float D[NN * NN];
    int tid = threadIdx.x;
    for (int k = tid; k < NN * NN; k += 256) {
        int i = k >> 6, j = k & 63;
        float d = 0.0f;
        if (i != j) {
            int h = (i < j) ? g_H[i * NN + j] : g_H[j * NN + i];
            float C = 1032192.0f - 4.0f * (float)h;   // 2K - 4H, K = 516096
            d = 1.0f - C * (1.0f / 2016.0f);
        }
        D[k] = d;
    }
    __syncthreads();
    float4* o = (float4*)(out + (size_t)blockIdx.x * (NN * NN));
    const float4* s = (const float4*)D;
    for (int k = tid; k < NN * NN / 4; k += 256) o[k] = s[k];
}

extern "C" void kernel_launch(void* const* d_in, const int* in_sizes, int n_in,
                              void* d_out, int out_size) {
    (void)in_sizes; (void)n_in; (void)out_size;
    const float* in = (const float*)d_in[0];
    float* out = (float*)d_out;

    void* hptr = nullptr;
    cudaGetSymbolAddress(&hptr, g_H);
    cudaMemsetAsync(hptr, 0, NN * NN * sizeof(int));

    fusedKD<<<TT, 512>>>(in);
    phase3<<<BB, 256>>>(out);
}

// round 5
// speedup vs baseline: 1.2466x; 1.2466x over previous
#include <cuda_runtime.h>
#include <stdint.h>

#define BB 64
#define TT 256
#define NN 64
#define NPAIRS 2016               // 64*63/2 batch pairs
#define WG_PER_T 63               // 32-pair words per t
#define XPAD 68                   // padded row stride (floats) for xs
#define ROWB (XPAD * 4)           // 272 bytes per xs row

__device__ int g_H[NN * NN];      // Hamming accumulators (only i<j used)

// ---------------- fused: sign-bit pack + XOR/popcount Gram, one block per t ----
__global__ __launch_bounds__(512) void fusedKD(const float* __restrict__ in) {
    __shared__ __align__(16) float xs[BB][XPAD];          // 17.4 KB padded slab
    __shared__ __align__(16) uint32_t bits[WG_PER_T][NN]; // 16.1 KB bit matrix
    __shared__ uint32_t pr[NPAIRS];                       // 8.1 KB byte-offset pairs
    int tid = threadIdx.x;
    int t = blockIdx.x;

    // Load 64x64 slab (float4, coalesced) into padded smem rows.
    {
        const float4* src = (const float4*)in;
        for (int q = tid; q < BB * 16; q += 512) {
            int b = q >> 4, c = q & 15;
            float4 v = src[(size_t)b * (TT * 16) + t * 16 + c];
            *(float4*)&xs[b][c * 4] = v;
        }
    }
    // Pair table: pr[p] = (a*272) | ((b*272) << 16), closed-form decode + fixup.
    for (int p = tid; p < NPAIRS; p += 512) {
        int a = (int)floorf(63.5f - sqrtf(4032.25f - 2.0f * (float)p));
        if (a < 0) a = 0; if (a > 62) a = 62;
        int cum = 63 * a - ((a * (a - 1)) >> 1);
        if (p < cum)               { a--; cum = 63 * a - ((a * (a - 1)) >> 1); }
        else if (p >= cum + 63 - a){ a++; cum = 63 * a - ((a * (a - 1)) >> 1); }
        int b = a + 1 + (p - cum);
        pr[p] = (uint32_t)(a * ROWB) | ((uint32_t)(b * ROWB) << 16);
    }
    __syncthreads();

    // Bit-pack: task = (wg, colgroup of 4). 63*16 = 1008 tasks, 4 cols/thread.
    for (int task = tid; task < WG_PER_T * 16; task += 512) {
        int wg = task >> 4, cg = task & 15;
        const uint32_t* prp = &pr[wg << 5];
        const char* xb = (const char*)xs + cg * 16;
        uint32_t w0 = 0, w1 = 0, w2 = 0, w3 = 0;
        #pragma unroll
        for (int s = 0; s < 32; s++) {
            uint32_t u = prp[s];
            float4 fa = *(const float4*)(xb + (u & 0xFFFFu));
            float4 fb = *(const float4*)(xb + (u >> 16));
            w0 |= (fa.x > fb.x) ? (1u << s) : 0u;
            w1 |= (fa.y > fb.y) ? (1u << s) : 0u;
            w2 |= (fa.z > fb.z) ? (1u << s) : 0u;
            w3 |= (fa.w > fb.w) ? (1u << s) : 0u;
        }
        *(uint4*)&bits[wg][cg << 2] = make_uint4(w0, w1, w2, w3);
    }
    __syncthreads();

    // Gram: 136 upper-triangle 4x4 tiles, 16 accumulators, full 63-word sweep.
    if (tid < 136) {
        int ti = 0, rem = tid;
        while (rem >= 16 - ti) { rem -= 16 - ti; ti++; }
        int tj = ti + rem;
        int i0 = ti << 2, j0 = tj << 2;

        int acc[16];
        #pragma unroll
        for (int k = 0; k < 16; k++) acc[k] = 0;

        #pragma unroll 3
        for (int w = 0; w < WG_PER_T; w++) {
            uint4 bi = *(const uint4*)&bits[w][i0];
            uint4 bj = *(const uint4*)&bits[w][j0];
            uint32_t iv[4] = {bi.x, bi.y, bi.z, bi.w};
            uint32_t jv[4] = {bj.x, bj.y, bj.z, bj.w};
            #pragma unroll
            for (int ii = 0; ii < 4; ii++)
                #pragma unroll
                for (int jj = 0; jj < 4; jj++)
                    acc[ii * 4 + jj] += __popc(iv[ii] ^ jv[jj]);
        }
        #pragma unroll
        for (int k = 0; k < 16; k++) {
            int i = i0 + (k >> 2), j = j0 + (k & 3);
            if (i < j) atomicAdd(&g_H[i * NN + j], acc[k]);  // fire-and-forget RED
        }
    }
}

// ---------------- distance + broadcast ----------------
// Stage H in shared (coalesced LDG), compute D from smem, vectorized broadcast.
// D[i,j] = 1 - C/2016, C = 1032192 - 4H (K = 516096 unordered samples), diag 0.
__global__ __launch_bounds__(256) void phase3(float* __restrict__ out) {
    __shared__ __align__(16) int   Hs[NN * NN];   // 16 KB
    __shared__ __align__(16) float D[NN * NN];    // 16 KB
    int tid = threadIdx.x;

    // Coalesced vector load of the full H matrix into shared.
    {
        const int4* src = (const int4*)g_H;
        int4* dst = (int4*)Hs;
        for (int k = tid; k < NN * NN / 4; k += 256) dst[k] = src[k];
    }
    __syncthreads();

    for (int k = tid; k < NN * NN; k += 256) {
        int i = k >> 6, j = k & 63;
        float d = 0.0f;
        if (i != j) {
            int h = (i < j) ? Hs[i * NN + j] : Hs[j * NN + i];  // smem scatter
            float C = 1032192.0f - 4.0f * (float)h;
            d = 1.0f - C * (1.0f / 2016.0f);
        }
        D[k] = d;
    }
    __syncthreads();

    float4* o = (float4*)(out + (size_t)blockIdx.x * (NN * NN));
    const float4* s = (const float4*)D;
    for (int k = tid; k < NN * NN / 4; k += 256) o[k] = s[k];
}

extern "C" void kernel_launch(void* const* d_in, const int* in_sizes, int n_in,
                              void* d_out, int out_size) {
    (void)in_sizes; (void)n_in; (void)out_size;
    const float* in = (const float*)d_in[0];
    float* out = (float*)d_out;

    void* hptr = nullptr;
    cudaGetSymbolAddress(&hptr, g_H);
    cudaMemsetAsync(hptr, 0, NN * NN * sizeof(int));

    fusedKD<<<TT, 512>>>(in);
    phase3<<<BB, 256>>>(out);
}